// round 1
// baseline (speedup 1.0000x reference)
#include <cuda_runtime.h>
#include <math.h>

// ---------------- problem constants ----------------
#define BATCH   64
#define SEQ     512
#define EMB     256
#define HID     512
#define GATES   2048           // 4*HID
#define VOCAB   50257
#define NBLK    128            // persistent LSTM grid (<=148 SMs, 1 block/SM)
#define HS_STRIDE 516          // padded h row stride in smem (bank-conflict free)

// ---------------- device scratch (static, no allocs) ----------------
__device__ float g_Z[(size_t)SEQ * BATCH * GATES];   // 256 MB: x@Wi + b, [s][b][4H]
__device__ float g_h[2][BATCH * HID];                // double-buffered hidden state
__device__ float g_y1[BATCH * HID];
__device__ float g_y2[BATCH * HID];
__device__ float g_logits[(size_t)BATCH * VOCAB];
__device__ unsigned g_bar_cnt   = 0;
__device__ unsigned g_bar_sense = 0;

// ---------------- grid barrier (sense reversing; state returns to 0) ----------
__device__ __forceinline__ void grid_barrier(unsigned &sense)
{
    __syncthreads();
    if (threadIdx.x == 0) {
        sense ^= 1u;
        __threadfence();
        if (atomicAdd(&g_bar_cnt, 1u) == NBLK - 1u) {
            atomicExch(&g_bar_cnt, 0u);
            __threadfence();
            atomicExch(&g_bar_sense, sense);
        } else {
            while (atomicAdd(&g_bar_sense, 0u) != sense) { }
        }
    }
    __syncthreads();
}

__device__ __forceinline__ float sigmoidf_(float x)
{
    return 1.0f / (1.0f + __expf(-x));
}

// ---------------- kernel 1: Z = gather(emb, inputs) @ Wi + b --------------
// grid (32, 512): x = N-tile (2048/64), y = M-tile (32768/64). 256 threads.
__global__ void __launch_bounds__(256)
embed_gemm_kernel(const int* __restrict__ inputs, const float* __restrict__ emb,
                  const float* __restrict__ Wi, const float* __restrict__ bias)
{
    __shared__ float As[64][36];   // [m][k] padded
    __shared__ float Bs[32][64];   // [k][n]

    const int t  = threadIdx.x;
    const int mt = blockIdx.y;     // 0..511
    const int nt = blockIdx.x;     // 0..31

    // A-load mapping: each thread loads 8 contiguous k for one row
    const int m_load = t >> 2;            // 0..63
    const int kb     = (t & 3) * 8;       // 0,8,16,24
    const int rowg   = mt * 64 + m_load;  // global row = s*64+b
    const int s      = rowg >> 6;
    const int b      = rowg & 63;
    const int token  = inputs[b * SEQ + s];
    const float* erow = emb + (size_t)token * EMB;

    const int tm = t >> 4;   // 0..15
    const int tn = t & 15;   // 0..15

    float acc[4][4];
#pragma unroll
    for (int i = 0; i < 4; ++i)
#pragma unroll
        for (int j = 0; j < 4; ++j) acc[i][j] = 0.0f;

    for (int k0 = 0; k0 < EMB; k0 += 32) {
        // load A tile (embedding gather)
        float4 a0 = *(const float4*)(erow + k0 + kb);
        float4 a1 = *(const float4*)(erow + k0 + kb + 4);
        As[m_load][kb + 0] = a0.x; As[m_load][kb + 1] = a0.y;
        As[m_load][kb + 2] = a0.z; As[m_load][kb + 3] = a0.w;
        As[m_load][kb + 4] = a1.x; As[m_load][kb + 5] = a1.y;
        As[m_load][kb + 6] = a1.z; As[m_load][kb + 7] = a1.w;
        // load B tile
#pragma unroll
        for (int j = 0; j < 8; ++j) {
            int q   = t + j * 256;
            int kr  = q >> 6;
            int col = q & 63;
            Bs[kr][col] = Wi[(size_t)(k0 + kr) * GATES + nt * 64 + col];
        }
        __syncthreads();
#pragma unroll
        for (int k = 0; k < 32; ++k) {
            float a0_ = As[tm * 4 + 0][k];
            float a1_ = As[tm * 4 + 1][k];
            float a2_ = As[tm * 4 + 2][k];
            float a3_ = As[tm * 4 + 3][k];
            float4 bv = *(const float4*)&Bs[k][tn * 4];
            acc[0][0] += a0_ * bv.x; acc[0][1] += a0_ * bv.y; acc[0][2] += a0_ * bv.z; acc[0][3] += a0_ * bv.w;
            acc[1][0] += a1_ * bv.x; acc[1][1] += a1_ * bv.y; acc[1][2] += a1_ * bv.z; acc[1][3] += a1_ * bv.w;
            acc[2][0] += a2_ * bv.x; acc[2][1] += a2_ * bv.y; acc[2][2] += a2_ * bv.z; acc[2][3] += a2_ * bv.w;
            acc[3][0] += a3_ * bv.x; acc[3][1] += a3_ * bv.y; acc[3][2] += a3_ * bv.z; acc[3][3] += a3_ * bv.w;
        }
        __syncthreads();
    }

    float4 bb = *(const float4*)(bias + nt * 64 + tn * 4);
#pragma unroll
    for (int i = 0; i < 4; ++i) {
        int row = mt * 64 + tm * 4 + i;
        float4 v;
        v.x = acc[i][0] + bb.x; v.y = acc[i][1] + bb.y;
        v.z = acc[i][2] + bb.z; v.w = acc[i][3] + bb.w;
        *(float4*)(g_Z + (size_t)row * GATES + nt * 64 + tn * 4) = v;
    }
}

// ---------------- kernel 2: persistent LSTM over 512 steps ----------------
// 128 blocks x 256 threads. Block owns 4 hidden units; Wh slice lives in SMEM
// for the whole kernel. Per thread: one (batch, unit) pair; c in register.
#define LSTM_SMEM ((BATCH * HS_STRIDE + HID * 16) * 4)

__global__ void __launch_bounds__(256, 1)
lstm_kernel(const float* __restrict__ Wh)
{
    extern __shared__ float sm[];
    float*  h_s   = sm;                                  // [64][HS_STRIDE]
    float4* Whs4  = (float4*)(sm + BATCH * HS_STRIDE);   // [512][4u] -> gates i,f,g,o

    const int tid  = threadIdx.x;
    const int blk  = blockIdx.x;
    const int lane = tid & 31;
    const int warp = tid >> 5;
    const int b    = warp * 8 + (lane >> 2);   // 0..63
    const int u    = lane & 3;                 // 0..3
    const int uu   = blk * 4 + u;              // global hidden unit

    // stage Wh slice: Whs4[k*4+u2] = {Wh[k][uu2], Wh[k][512+uu2], Wh[k][1024+uu2], Wh[k][1536+uu2]}
    for (int i = tid; i < HID * 4; i += 256) {
        int k   = i >> 2;
        int u2  = i & 3;
        int col = blk * 4 + u2;
        const float* w = Wh + (size_t)k * GATES + col;
        Whs4[i] = make_float4(w[0], w[512], w[1024], w[1536]);
    }

    float c = 0.0f;
    unsigned sense = 0;
    __syncthreads();

    for (int s = 0; s < SEQ; ++s) {
        // stage h_{s-1} into smem (L2-coherent loads; bypass L1)
        if (s == 0) {
            float4 z4 = make_float4(0.f, 0.f, 0.f, 0.f);
            for (int q = tid; q < BATCH * HID / 4; q += 256) {
                int bb = q >> 7, k4 = q & 127;
                ((float4*)&h_s[bb * HS_STRIDE])[k4] = z4;
            }
        } else {
            const float4* src = (const float4*)g_h[s & 1];
            for (int q = tid; q < BATCH * HID / 4; q += 256) {
                int bb = q >> 7, k4 = q & 127;
                ((float4*)&h_s[bb * HS_STRIDE])[k4] = __ldcg(src + q);
            }
        }
        __syncthreads();

        const float* z = g_Z + ((size_t)s * BATCH + b) * GATES + uu;
        float ai = z[0], af = z[512], ag = z[1024], ao = z[1536];

        const float4* hr = (const float4*)&h_s[b * HS_STRIDE];
#pragma unroll 8
        for (int k4 = 0; k4 < 128; ++k4) {
            float4 hv = hr[k4];
            int kb = k4 * 16 + u;
            float4 w;
            w = Whs4[kb +  0]; ai += hv.x * w.x; af += hv.x * w.y; ag += hv.x * w.z; ao += hv.x * w.w;
            w = Whs4[kb +  4]; ai += hv.y * w.x; af += hv.y * w.y; ag += hv.y * w.z; ao += hv.y * w.w;
            w = Whs4[kb +  8]; ai += hv.z * w.x; af += hv.z * w.y; ag += hv.z * w.z; ao += hv.z * w.w;
            w = Whs4[kb + 12]; ai += hv.w * w.x; af += hv.w * w.y; ag += hv.w * w.z; ao += hv.w * w.w;
        }

        float ig = sigmoidf_(ai);
        float fg = sigmoidf_(af);
        float gg = tanhf(ag);
        float og = sigmoidf_(ao);
        c = fg * c + ig * gg;
        float hv = og * tanhf(c);

        g_h[(s + 1) & 1][b * HID + uu] = hv;   // step s writes buf (s+1)&1; final h in g_h[0]

        grid_barrier(sense);
    }
}

// ---------------- kernel 3/4: y = tanh(x @ W + bias), 64x512 ----------------
__global__ void __launch_bounds__(256)
fc_tanh_kernel(const float* __restrict__ x, const float* __restrict__ W,
               const float* __restrict__ bias, float* __restrict__ y)
{
    int o = blockIdx.x * blockDim.x + threadIdx.x;   // 32768 threads
    int b = o >> 9, j = o & 511;
    const float* xr = x + b * HID;
    float a0 = 0.f, a1 = 0.f, a2 = 0.f, a3 = 0.f;
#pragma unroll 4
    for (int k = 0; k < HID; k += 4) {
        a0 += xr[k + 0] * W[(size_t)(k + 0) * HID + j];
        a1 += xr[k + 1] * W[(size_t)(k + 1) * HID + j];
        a2 += xr[k + 2] * W[(size_t)(k + 2) * HID + j];
        a3 += xr[k + 3] * W[(size_t)(k + 3) * HID + j];
    }
    y[o] = tanhf((a0 + a1) + (a2 + a3) + bias[j]);
}

// ---------------- kernel 5: logits = y2 @ W3 + b3 ----------------
// 128 threads/block, 1 vocab column per thread, 64 batch accumulators in regs.
__global__ void __launch_bounds__(128)
logits_kernel(const float* __restrict__ y, const float* __restrict__ W3,
              const float* __restrict__ b3, float* __restrict__ out)
{
    __shared__ float ys[128][68];   // [k-chunk][b] transposed, padded
    const int j = blockIdx.x * 128 + threadIdx.x;

    float acc[64];
#pragma unroll
    for (int b = 0; b < 64; ++b) acc[b] = 0.0f;

    for (int kc = 0; kc < HID; kc += 128) {
        __syncthreads();
        for (int q = threadIdx.x; q < 128 * 64; q += 128) {
            int b = q >> 7, k = q & 127;
            ys[k][b] = y[b * HID + kc + k];
        }
        __syncthreads();
        if (j < VOCAB) {
#pragma unroll 4
            for (int k = 0; k < 128; ++k) {
                float w = W3[(size_t)(kc + k) * VOCAB + j];
                const float4* yr = (const float4*)&ys[k][0];
#pragma unroll
                for (int b4 = 0; b4 < 16; ++b4) {
                    float4 v = yr[b4];
                    acc[b4 * 4 + 0] += v.x * w;
                    acc[b4 * 4 + 1] += v.y * w;
                    acc[b4 * 4 + 2] += v.z * w;
                    acc[b4 * 4 + 3] += v.w * w;
                }
            }
        }
    }
    if (j < VOCAB) {
        float bb = b3[j];
#pragma unroll
        for (int b = 0; b < 64; ++b)
            out[(size_t)b * VOCAB + j] = acc[b] + bb;
    }
}

// ---------------- kernel 6: row-wise log_softmax ----------------
__global__ void __launch_bounds__(1024)
logsoftmax_kernel(const float* __restrict__ logits, float* __restrict__ out)
{
    __shared__ float red[32];
    const int b = blockIdx.x;
    const float* row  = logits + (size_t)b * VOCAB;
    float*       orow = out    + (size_t)b * VOCAB;
    const int tid = threadIdx.x;

    float m = -1e30f;
    for (int j = tid; j < VOCAB; j += 1024) m = fmaxf(m, row[j]);
#pragma unroll
    for (int o = 16; o; o >>= 1) m = fmaxf(m, __shfl_xor_sync(0xffffffffu, m, o));
    if ((tid & 31) == 0) red[tid >> 5] = m;
    __syncthreads();
    if (tid < 32) {
        float v = red[tid];
#pragma unroll
        for (int o = 16; o; o >>= 1) v = fmaxf(v, __shfl_xor_sync(0xffffffffu, v, o));
        red[tid] = v;
    }
    __syncthreads();
    m = red[0];

    float sum = 0.0f;
    for (int j = tid; j < VOCAB; j += 1024) sum += __expf(row[j] - m);
#pragma unroll
    for (int o = 16; o; o >>= 1) sum += __shfl_xor_sync(0xffffffffu, sum, o);
    __syncthreads();
    if ((tid & 31) == 0) red[tid >> 5] = sum;
    __syncthreads();
    if (tid < 32) {
        float v = red[tid];
#pragma unroll
        for (int o = 16; o; o >>= 1) v += __shfl_xor_sync(0xffffffffu, v, o);
        red[tid] = v;
    }
    __syncthreads();
    float lse = m + logf(red[0]);

    for (int j = tid; j < VOCAB; j += 1024) orow[j] = row[j] - lse;
}

// ---------------- launch ----------------
extern "C" void kernel_launch(void* const* d_in, const int* in_sizes, int n_in,
                              void* d_out, int out_size)
{
    const int*   inputs = (const int*)  d_in[0];
    const float* emb    = (const float*)d_in[1];
    const float* Wi     = (const float*)d_in[2];
    const float* Wh     = (const float*)d_in[3];
    const float* bvec   = (const float*)d_in[4];
    const float* W1     = (const float*)d_in[5];
    const float* b1     = (const float*)d_in[6];
    const float* W2     = (const float*)d_in[7];
    const float* b2     = (const float*)d_in[8];
    const float* W3     = (const float*)d_in[9];
    const float* b3     = (const float*)d_in[10];
    float* out = (float*)d_out;

    void *p_h = 0, *p_y1 = 0, *p_y2 = 0, *p_lg = 0;
    cudaGetSymbolAddress(&p_h,  g_h);
    cudaGetSymbolAddress(&p_y1, g_y1);
    cudaGetSymbolAddress(&p_y2, g_y2);
    cudaGetSymbolAddress(&p_lg, g_logits);

    // 1. Z = emb[inputs] @ Wi + b  (time-parallel)
    embed_gemm_kernel<<<dim3(GATES / 64, (SEQ * BATCH) / 64), 256>>>(inputs, emb, Wi, bvec);

    // 2. persistent LSTM recurrence
    cudaFuncSetAttribute(lstm_kernel, cudaFuncAttributeMaxDynamicSharedMemorySize, LSTM_SMEM);
    lstm_kernel<<<NBLK, 256, LSTM_SMEM>>>(Wh);

    // 3/4. dense tanh layers (final h is g_h[0])
    fc_tanh_kernel<<<128, 256>>>((const float*)p_h,  W1, b1, (float*)p_y1);
    fc_tanh_kernel<<<128, 256>>>((const float*)p_y1, W2, b2, (float*)p_y2);

    // 5. vocab projection
    logits_kernel<<<(VOCAB + 127) / 128, 128>>>((const float*)p_y2, W3, b3, (float*)p_lg);

    // 6. log_softmax
    logsoftmax_kernel<<<BATCH, 1024>>>((const float*)p_lg, out);
}

// round 2
// speedup vs baseline: 1.5733x; 1.5733x over previous
#include <cuda_runtime.h>
#include <math.h>

// ---------------- problem constants ----------------
#define BATCH   64
#define SEQ     512
#define EMB     256
#define HID     512
#define GATES   2048           // 4*HID
#define VOCAB   50257
#define NBLK    128            // persistent LSTM grid (<=148 SMs, 1 block/SM)

// ---------------- device scratch (static, no allocs) ----------------
__device__ float g_Z[(size_t)SEQ * BATCH * GATES];   // 256 MB: x@Wi + b, [s][b][4H]
__device__ float g_hT[2][HID * BATCH];               // hidden state, TRANSPOSED [unit][batch]
__device__ float g_y1[BATCH * HID];
__device__ float g_y2[BATCH * HID];
__device__ float g_logits[(size_t)BATCH * VOCAB];
__device__ unsigned g_bar_cnt   = 0;
__device__ unsigned g_bar_sense = 0;

// ---------------- packed f32x2 helpers (FFMA2 path, sm_100+) --------------
__device__ __forceinline__ unsigned long long fma2(unsigned long long a,
                                                   unsigned long long b,
                                                   unsigned long long c)
{
    unsigned long long d;
    asm("fma.rn.f32x2 %0, %1, %2, %3;" : "=l"(d) : "l"(a), "l"(b), "l"(c));
    return d;
}
__device__ __forceinline__ unsigned long long pack2(float x)
{
    unsigned long long d;
    unsigned u = __float_as_uint(x);
    asm("mov.b64 %0, {%1, %1};" : "=l"(d) : "r"(u));
    return d;
}
__device__ __forceinline__ float lo2(unsigned long long v) { return __uint_as_float((unsigned)v); }
__device__ __forceinline__ float hi2(unsigned long long v) { return __uint_as_float((unsigned)(v >> 32)); }

// ---------------- grid barrier (sense reversing; cheap volatile poll) ------
__device__ __forceinline__ void grid_barrier(unsigned &sense)
{
    __syncthreads();
    if (threadIdx.x == 0) {
        sense ^= 1u;
        __threadfence();
        if (atomicAdd(&g_bar_cnt, 1u) == NBLK - 1u) {
            atomicExch(&g_bar_cnt, 0u);
            __threadfence();
            atomicExch(&g_bar_sense, sense);
        } else {
            while (((volatile unsigned*)&g_bar_sense)[0] != sense) { }
            __threadfence();
        }
    }
    __syncthreads();
}

__device__ __forceinline__ float sigmoidf_(float x)
{
    return 1.0f / (1.0f + __expf(-x));
}

// ---------------- kernel 1: Z = gather(emb, inputs) @ Wi + b --------------
// 128x128 block tile, K-chunks of 16, 8x8 thread tile via f32x2.
// grid (16, 256), 256 threads.
__global__ void __launch_bounds__(256)
embed_gemm_kernel(const int* __restrict__ inputs, const float* __restrict__ emb,
                  const float* __restrict__ Wi, const float* __restrict__ bias)
{
    __shared__ float As[128][17];    // [m][k], pad 17 -> conflict-free loader STS
    __shared__ float Bs[16][132];    // [k][n]

    const int t  = threadIdx.x;
    const int mt = blockIdx.y;       // 0..255
    const int nt = blockIdx.x;       // 0..15
    const int tx = t & 15;           // n dir
    const int ty = t >> 4;           // m dir

    // A loader: row ra = t>>1, k-offset (t&1)*8 (embedding gather)
    const int ra   = t >> 1;
    const int koff = (t & 1) * 8;
    const int rowg = mt * 128 + ra;
    const int s    = rowg >> 6;
    const int b    = rowg & 63;
    const float* erow = emb + (size_t)inputs[b * SEQ + s] * EMB;

    // B loader: kr = t>>4, col = (t&15)*8
    const int bkr  = t >> 4;
    const int bcol = (t & 15) * 8;

    unsigned long long acc[8][4];
#pragma unroll
    for (int i = 0; i < 8; ++i)
#pragma unroll
        for (int j = 0; j < 4; ++j) acc[i][j] = 0ULL;

    for (int k0 = 0; k0 < EMB; k0 += 16) {
        // load A tile
        {
            float4 a0 = *(const float4*)(erow + k0 + koff);
            float4 a1 = *(const float4*)(erow + k0 + koff + 4);
            As[ra][koff + 0] = a0.x; As[ra][koff + 1] = a0.y;
            As[ra][koff + 2] = a0.z; As[ra][koff + 3] = a0.w;
            As[ra][koff + 4] = a1.x; As[ra][koff + 5] = a1.y;
            As[ra][koff + 6] = a1.z; As[ra][koff + 7] = a1.w;
        }
        // load B tile
        {
            const float* wsrc = Wi + (size_t)(k0 + bkr) * GATES + nt * 128 + bcol;
            float4 b0v = *(const float4*)(wsrc);
            float4 b1v = *(const float4*)(wsrc + 4);
            *(float4*)&Bs[bkr][bcol]     = b0v;
            *(float4*)&Bs[bkr][bcol + 4] = b1v;
        }
        __syncthreads();

#pragma unroll
        for (int k = 0; k < 16; ++k) {
            unsigned long long pa[8];
#pragma unroll
            for (int i = 0; i < 4; ++i) {
                pa[i]     = pack2(As[ty * 4 + i][k]);
                pa[i + 4] = pack2(As[64 + ty * 4 + i][k]);
            }
            ulonglong2 b0v = *(const ulonglong2*)&Bs[k][tx * 4];
            ulonglong2 b1v = *(const ulonglong2*)&Bs[k][64 + tx * 4];
#pragma unroll
            for (int i = 0; i < 8; ++i) {
                acc[i][0] = fma2(pa[i], b0v.x, acc[i][0]);
                acc[i][1] = fma2(pa[i], b0v.y, acc[i][1]);
                acc[i][2] = fma2(pa[i], b1v.x, acc[i][2]);
                acc[i][3] = fma2(pa[i], b1v.y, acc[i][3]);
            }
        }
        __syncthreads();
    }

    float4 bb0 = *(const float4*)(bias + nt * 128 + tx * 4);
    float4 bb1 = *(const float4*)(bias + nt * 128 + 64 + tx * 4);
#pragma unroll
    for (int i = 0; i < 8; ++i) {
        int row = mt * 128 + ((i < 4) ? (ty * 4 + i) : (64 + ty * 4 + i - 4));
        float* zr = g_Z + (size_t)row * GATES + nt * 128;
        float4 v0, v1;
        v0.x = lo2(acc[i][0]) + bb0.x; v0.y = hi2(acc[i][0]) + bb0.y;
        v0.z = lo2(acc[i][1]) + bb0.z; v0.w = hi2(acc[i][1]) + bb0.w;
        v1.x = lo2(acc[i][2]) + bb1.x; v1.y = hi2(acc[i][2]) + bb1.y;
        v1.z = lo2(acc[i][3]) + bb1.z; v1.w = hi2(acc[i][3]) + bb1.w;
        *(float4*)(zr + tx * 4)      = v0;
        *(float4*)(zr + 64 + tx * 4) = v1;
    }
}

// ---------------- kernel 2: persistent LSTM over 512 steps ----------------
// 128 blocks x 256 threads, 1 block/SM. Block owns 4 hidden units.
// h transposed in smem: h_s[k][b]. Thread = (k-chunk kc, unit u, 4 batches).
// Gates packed (i,f) / (g,o) into f32x2 accumulators; k-split-4 reduced in smem.
#define LSTM_SMEM (131072 + 32768 + 16384)

__global__ void __launch_bounds__(256, 1)
lstm_kernel(const float* __restrict__ Wh)
{
    extern __shared__ float sm[];
    float*       h_s  = sm;                                   // [512][64]
    float4*      Whs4 = (float4*)(sm + 32768);                // [512][4u]: {wi,wf,wg,wo}
    ulonglong2*  red  = (ulonglong2*)(sm + 32768 + 8192);     // [4kc][64 r][4 bi]

    const int tid = threadIdx.x;
    const int kc  = tid >> 6;            // k-chunk 0..3
    const int u   = tid & 3;             // unit within block
    const int bg  = (tid >> 2) & 15;     // batch group (warp-safe mapping)
    const int b0  = bg * 4;
    const int uu  = blockIdx.x * 4 + u;

    // stage Wh slice (one-time): Whs4[k*4+u2] = Wh[k][{0,512,1024,1536}+col]
    for (int i = tid; i < HID * 4; i += 256) {
        int k   = i >> 2;
        int u2  = i & 3;
        int col = blockIdx.x * 4 + u2;
        const float* w = Wh + (size_t)k * GATES + col;
        Whs4[i] = make_float4(w[0], w[512], w[1024], w[1536]);
    }

    float c[4] = {0.f, 0.f, 0.f, 0.f};   // owned by tid<64 threads
    unsigned sense = 0;
    __syncthreads();

    for (int s = 0; s < SEQ; ++s) {
        // stage h_{s-1} (k-major broadcast from L2)
        if (s > 0) {
            const float4* src = (const float4*)g_hT[s & 1];
            float4* dst = (float4*)h_s;
#pragma unroll
            for (int q = 0; q < 32; ++q)
                dst[tid + q * 256] = __ldcg(src + tid + q * 256);
        }

        // prefetch Z gates (only reducer threads need them)
        float zi[4], zf[4], zg[4], zo[4];
        if (kc == 0) {
            const float* zb = g_Z + (size_t)s * BATCH * GATES + uu;
#pragma unroll
            for (int bi = 0; bi < 4; ++bi) {
                const float* z = zb + (size_t)(b0 + bi) * GATES;
                zi[bi] = z[0];    zf[bi] = z[512];
                zg[bi] = z[1024]; zo[bi] = z[1536];
            }
        }
        __syncthreads();

        unsigned long long aif0 = 0, aif1 = 0, aif2 = 0, aif3 = 0;
        unsigned long long ago0 = 0, ago1 = 0, ago2 = 0, ago3 = 0;

        if (s > 0) {
            const ulonglong2* wrow = (const ulonglong2*)Whs4;
            const float4*     hrow = (const float4*)h_s;
            const int kbeg = kc * 128;
#pragma unroll 4
            for (int k = kbeg; k < kbeg + 128; ++k) {
                ulonglong2 w  = wrow[k * 4 + u];     // .x = (wi,wf)  .y = (wg,wo)
                float4     h4 = hrow[k * 16 + bg];   // 4 batches
                unsigned long long p;
                p = pack2(h4.x); aif0 = fma2(p, w.x, aif0); ago0 = fma2(p, w.y, ago0);
                p = pack2(h4.y); aif1 = fma2(p, w.x, aif1); ago1 = fma2(p, w.y, ago1);
                p = pack2(h4.z); aif2 = fma2(p, w.x, aif2); ago2 = fma2(p, w.y, ago2);
                p = pack2(h4.w); aif3 = fma2(p, w.x, aif3); ago3 = fma2(p, w.y, ago3);
            }
        }

        // write partials: red[(kc*64 + r)*4 + bi] == red[tid*4 + bi]
        {
            ulonglong2* rs = red + (size_t)tid * 4;
            rs[0] = make_ulonglong2(aif0, ago0);
            rs[1] = make_ulonglong2(aif1, ago1);
            rs[2] = make_ulonglong2(aif2, ago2);
            rs[3] = make_ulonglong2(aif3, ago3);
        }
        __syncthreads();

        if (tid < 64) {
            float hv[4];
#pragma unroll
            for (int bi = 0; bi < 4; ++bi) {
                float ai = zi[bi], af = zf[bi], ag = zg[bi], ao = zo[bi];
#pragma unroll
                for (int kk = 0; kk < 4; ++kk) {
                    ulonglong2 v = red[(size_t)(kk * 64 + tid) * 4 + bi];
                    ai += lo2(v.x); af += hi2(v.x);
                    ag += lo2(v.y); ao += hi2(v.y);
                }
                float ig = sigmoidf_(ai);
                float fg = sigmoidf_(af);
                float gg = tanhf(ag);
                float og = sigmoidf_(ao);
                c[bi] = fg * c[bi] + ig * gg;
                hv[bi] = og * tanhf(c[bi]);
            }
            *(float4*)(g_hT[(s + 1) & 1] + uu * 64 + b0) =
                make_float4(hv[0], hv[1], hv[2], hv[3]);
        }

        grid_barrier(sense);
    }
}

// ---------------- kernels 3/4: y = tanh(x @ W + bias), 64x512 --------------
// SK/SB: element strides of x along k and b (lets fc1 read transposed g_hT).
template<int SK, int SB>
__global__ void __launch_bounds__(256)
fc_tanh_kernel(const float* __restrict__ x, const float* __restrict__ W,
               const float* __restrict__ bias, float* __restrict__ y)
{
    int o = blockIdx.x * blockDim.x + threadIdx.x;   // 32768 threads
    int b = o >> 9, j = o & 511;
    const float* xp = x + b * SB;
    float a0 = 0.f, a1 = 0.f, a2 = 0.f, a3 = 0.f;
#pragma unroll 4
    for (int k = 0; k < HID; k += 4) {
        a0 += xp[(k + 0) * SK] * W[(size_t)(k + 0) * HID + j];
        a1 += xp[(k + 1) * SK] * W[(size_t)(k + 1) * HID + j];
        a2 += xp[(k + 2) * SK] * W[(size_t)(k + 2) * HID + j];
        a3 += xp[(k + 3) * SK] * W[(size_t)(k + 3) * HID + j];
    }
    y[o] = tanhf((a0 + a1) + (a2 + a3) + bias[j]);
}

// ---------------- kernel 5: logits = y2 @ W3 + b3 ----------------
__global__ void __launch_bounds__(128)
logits_kernel(const float* __restrict__ y, const float* __restrict__ W3,
              const float* __restrict__ b3, float* __restrict__ out)
{
    __shared__ float ys[128][68];   // [k-chunk][b] transposed, padded
    const int j = blockIdx.x * 128 + threadIdx.x;

    float acc[64];
#pragma unroll
    for (int b = 0; b < 64; ++b) acc[b] = 0.0f;

    for (int kc = 0; kc < HID; kc += 128) {
        __syncthreads();
        for (int q = threadIdx.x; q < 128 * 64; q += 128) {
            int b = q >> 7, k = q & 127;
            ys[k][b] = y[b * HID + kc + k];
        }
        __syncthreads();
        if (j < VOCAB) {
#pragma unroll 4
            for (int k = 0; k < 128; ++k) {
                float w = W3[(size_t)(kc + k) * VOCAB + j];
                const float4* yr = (const float4*)&ys[k][0];
#pragma unroll
                for (int b4 = 0; b4 < 16; ++b4) {
                    float4 v = yr[b4];
                    acc[b4 * 4 + 0] += v.x * w;
                    acc[b4 * 4 + 1] += v.y * w;
                    acc[b4 * 4 + 2] += v.z * w;
                    acc[b4 * 4 + 3] += v.w * w;
                }
            }
        }
    }
    if (j < VOCAB) {
        float bb = b3[j];
#pragma unroll
        for (int b = 0; b < 64; ++b)
            out[(size_t)b * VOCAB + j] = acc[b] + bb;
    }
}

// ---------------- kernel 6: row-wise log_softmax ----------------
__global__ void __launch_bounds__(1024)
logsoftmax_kernel(const float* __restrict__ logits, float* __restrict__ out)
{
    __shared__ float red[32];
    const int b = blockIdx.x;
    const float* row  = logits + (size_t)b * VOCAB;
    float*       orow = out    + (size_t)b * VOCAB;
    const int tid = threadIdx.x;

    float m = -1e30f;
    for (int j = tid; j < VOCAB; j += 1024) m = fmaxf(m, row[j]);
#pragma unroll
    for (int o = 16; o; o >>= 1) m = fmaxf(m, __shfl_xor_sync(0xffffffffu, m, o));
    if ((tid & 31) == 0) red[tid >> 5] = m;
    __syncthreads();
    if (tid < 32) {
        float v = red[tid];
#pragma unroll
        for (int o = 16; o; o >>= 1) v = fmaxf(v, __shfl_xor_sync(0xffffffffu, v, o));
        red[tid] = v;
    }
    __syncthreads();
    m = red[0];

    float sum = 0.0f;
    for (int j = tid; j < VOCAB; j += 1024) sum += __expf(row[j] - m);
#pragma unroll
    for (int o = 16; o; o >>= 1) sum += __shfl_xor_sync(0xffffffffu, sum, o);
    __syncthreads();
    if ((tid & 31) == 0) red[tid >> 5] = sum;
    __syncthreads();
    if (tid < 32) {
        float v = red[tid];
#pragma unroll
        for (int o = 16; o; o >>= 1) v += __shfl_xor_sync(0xffffffffu, v, o);
        red[tid] = v;
    }
    __syncthreads();
    float lse = m + logf(red[0]);

    for (int j = tid; j < VOCAB; j += 1024) orow[j] = row[j] - lse;
}

// ---------------- launch ----------------
extern "C" void kernel_launch(void* const* d_in, const int* in_sizes, int n_in,
                              void* d_out, int out_size)
{
    const int*   inputs = (const int*)  d_in[0];
    const float* emb    = (const float*)d_in[1];
    const float* Wi     = (const float*)d_in[2];
    const float* Wh     = (const float*)d_in[3];
    const float* bvec   = (const float*)d_in[4];
    const float* W1     = (const float*)d_in[5];
    const float* b1     = (const float*)d_in[6];
    const float* W2     = (const float*)d_in[7];
    const float* b2     = (const float*)d_in[8];
    const float* W3     = (const float*)d_in[9];
    const float* b3     = (const float*)d_in[10];
    float* out = (float*)d_out;

    void *p_h = 0, *p_y1 = 0, *p_y2 = 0, *p_lg = 0;
    cudaGetSymbolAddress(&p_h,  g_hT);     // final h lives in g_hT[0] (transposed)
    cudaGetSymbolAddress(&p_y1, g_y1);
    cudaGetSymbolAddress(&p_y2, g_y2);
    cudaGetSymbolAddress(&p_lg, g_logits);

    // 1. Z = emb[inputs] @ Wi + b  (time-parallel)
    embed_gemm_kernel<<<dim3(GATES / 128, (SEQ * BATCH) / 128), 256>>>(inputs, emb, Wi, bvec);

    // 2. persistent LSTM recurrence
    cudaFuncSetAttribute(lstm_kernel, cudaFuncAttributeMaxDynamicSharedMemorySize, LSTM_SMEM);
    lstm_kernel<<<NBLK, 256, LSTM_SMEM>>>(Wh);

    // 3/4. dense tanh layers (fc1 reads transposed h)
    fc_tanh_kernel<64, 1><<<128, 256>>>((const float*)p_h,  W1, b1, (float*)p_y1);
    fc_tanh_kernel<1, 512><<<128, 256>>>((const float*)p_y1, W2, b2, (float*)p_y2);

    // 5. vocab projection
    logits_kernel<<<(VOCAB + 127) / 128, 128>>>((const float*)p_y2, W3, b3, (float*)p_lg);

    // 6. log_softmax
    logsoftmax_kernel<<<BATCH, 1024>>>((const float*)p_lg, out);
}